// round 16
// baseline (speedup 1.0000x reference)
#include <cuda_runtime.h>

// GyroLoss forward — R15 (BCH-8 + quat epilogue, 2 half-groups/thread,
// front-batched loads) with __launch_bounds__(256,3): ~85-reg budget so ptxas
// actually keeps all 14 loads in flight and interleaves the two BCH scans.

#define DT_F 0.01f
#define HUBER_F 0.005f
#define NPER4 2048
#define NPER5 1024
#define N0 5
#define TPB 256
#define HALF_STRIDE 131072

__device__ double g_sum4 = 0.0;
__device__ double g_sum5 = 0.0;
__device__ unsigned int g_count = 0u;

__device__ __forceinline__ void qmul(const float a[4], const float b[4], float c[4]) {
    c[0] = a[0]*b[0] - a[1]*b[1] - a[2]*b[2] - a[3]*b[3];
    c[1] = a[0]*b[1] + a[1]*b[0] + a[2]*b[3] - a[3]*b[2];
    c[2] = a[0]*b[2] - a[1]*b[3] + a[2]*b[0] + a[3]*b[1];
    c[3] = a[0]*b[3] + a[1]*b[2] - a[2]*b[1] + a[3]*b[0];
}

// c = conj(a) ⊗ b
__device__ __forceinline__ void qcmul(const float a[4], const float b[4], float c[4]) {
    c[0] = a[0]*b[0] + a[1]*b[1] + a[2]*b[2] + a[3]*b[3];
    c[1] = a[0]*b[1] - a[1]*b[0] - a[2]*b[3] + a[3]*b[2];
    c[2] = a[0]*b[2] + a[1]*b[3] - a[2]*b[0] - a[3]*b[1];
    c[3] = a[0]*b[3] - a[1]*b[2] + a[2]*b[1] - a[3]*b[0];
}

__device__ __forceinline__ void qexp_phi_small(float x, float y, float z, float q[4]) {
    float sq = x*x + y*y + z*z;
    float hq = 0.25f * sq;
    q[0] = 1.0f + hq * (-0.5f + hq * (1.0f / 24.0f));
    float sf = 0.5f * (1.0f + hq * (-(1.0f / 6.0f) + hq * (1.0f / 120.0f)));
    q[1] = sf * x; q[2] = sf * y; q[3] = sf * z;
}

__device__ __forceinline__ void qexp_full(float x, float y, float z, float q[4]) {
    float sq = x*x + y*y + z*z;
    float a = sq * __frsqrt_rn(fmaxf(sq, 1e-16f));
    float h = 0.5f * a;
    float sh = __sinf(h), ch = __cosf(h);
    float sf = __fdividef(sh, fmaxf(a, 1e-8f));
    q[0] = ch; q[1] = sf * x; q[2] = sf * y; q[3] = sf * z;
}

__device__ __forceinline__ float fast_atan01(float x) {
    float t = x * x;
    float p = -0.0117212f;
    p = fmaf(p, t,  0.05265332f);
    p = fmaf(p, t, -0.11643287f);
    p = fmaf(p, t,  0.19354346f);
    p = fmaf(p, t, -0.33262347f);
    p = fmaf(p, t,  0.99997726f);
    return x * p;
}

__device__ __forceinline__ float huber3_qlog(const float q[4]) {
    float w = q[0], x = q[1], y = q[2], z = q[3];
    float sg = (w < 0.0f) ? -1.0f : 1.0f;
    w *= sg; x *= sg; y *= sg; z *= sg;
    float nv2 = x*x + y*y + z*z;
    float nv = nv2 * __frsqrt_rn(fmaxf(nv2, 1e-24f));
    float lo = fminf(nv, w), hi = fmaxf(nv, w);
    float at = fast_atan01(__fdividef(lo, hi));
    float th = 2.0f * ((nv <= w) ? at : (1.57079632679f - at));
    float f = __fdividef(th, fmaxf(nv, 1e-20f)) * (1.0f / HUBER_F);
    float acc = 0.0f;
#pragma unroll
    for (int t = 0; t < 3; t++) {
        float zz = f * ((t == 0) ? x : (t == 1) ? y : z);
        float az = fabsf(zz);
        acc += (az < 1.0f) ? (0.5f * zz * zz) : (az - 0.5f);
    }
    return acc;
}

// BCH suffix-scan step (reverse time order): C += w x S; S += w
__device__ __forceinline__ void bch_step(float wx, float wy, float wz,
                                         float S[3], float C[3]) {
    C[0] = fmaf(wy, S[2], fmaf(-wz, S[1], C[0]));
    C[1] = fmaf(wz, S[0], fmaf(-wx, S[2], C[1]));
    C[2] = fmaf(wx, S[1], fmaf(-wy, S[0], C[2]));
    S[0] += wx; S[1] += wy; S[2] += wz;
}

// one half-group's full compute: accumulates s4/s5 for this thread's role
__device__ __forceinline__ void compute_half(int t, int lane,
        float4 f0, float4 f1, float4 f2, float4 f3, float4 f4, float4 f5,
        float4 xv, float& s4, float& s5) {
    // BCH-2 suffix scan over 8 raw increments (reverse time order)
    float S[3], C[3];
    S[0] = f5.y; S[1] = f5.z; S[2] = f5.w;           // incr 7
    C[0] = 0.0f; C[1] = 0.0f; C[2] = 0.0f;
    bch_step(f4.z, f4.w, f5.x, S, C);   // incr 6
    bch_step(f3.w, f4.x, f4.y, S, C);   // incr 5
    bch_step(f3.x, f3.y, f3.z, S, C);   // incr 4
    bch_step(f2.y, f2.z, f2.w, S, C);   // incr 3
    bch_step(f1.z, f1.w, f2.x, S, C);   // incr 2
    bch_step(f0.w, f1.x, f1.y, S, C);   // incr 1
    bch_step(f0.x, f0.y, f0.z, S, C);   // incr 0
    float q8[4];
    qexp_phi_small(fmaf(0.5f * DT_F * DT_F, C[0], DT_F * S[0]),
                   fmaf(0.5f * DT_F * DT_F, C[1], DT_F * S[1]),
                   fmaf(0.5f * DT_F * DT_F, C[2], DT_F * S[2]), q8);

    // 16-group: even lane combines with odd partner
    float q16[4];
    {
        float qp[4];
#pragma unroll
        for (int k = 0; k < 4; k++)
            qp[k] = __shfl_down_sync(0xFFFFFFFFu, q8[k], 1);
        qmul(q8, qp, q16);                           // valid on even lanes
    }

    // ground-truth quat (pair lanes broadcast same float4)
    float qR[4];
    qexp_full(xv.x, xv.y, xv.z, qR);

    // level-5 operands: gather within lane quad
    int lb = lane & ~3;
    float q32[4], qR32[4];
    {
        float qa[4], qb[4], ra[4];
#pragma unroll
        for (int k = 0; k < 4; k++) {
            qa[k] = __shfl_sync(0xFFFFFFFFu, q16[k], lb);
            qb[k] = __shfl_sync(0xFFFFFFFFu, q16[k], lb | 2);
            ra[k] = __shfl_sync(0xFFFFFFFFu, qR[k],  lb);
        }
        qmul(qa, qb, q32);                           // used on lane ≡3
        qmul(ra, qR, qR32);                          // lane3's own qR = group 2j+1
    }

    // converged relative-rotation log + huber
    int m = t & 3;
    float relA[4], relB[4], rel[4];
    qcmul(q16, qR, relA);                            // level-4 (even lanes)
    qcmul(q32, qR32, relB);                          // level-5 (lane ≡3)
#pragma unroll
    for (int k = 0; k < 4; k++) rel[k] = (m == 3) ? relB[k] : relA[k];
    float h = huber3_qlog(rel);

    if ((m & 1) == 0) {                              // lanes ≡0,2: level-4
        int i4 = (t >> 1) & (NPER4 - 1);
        if (i4 >= N0) s4 += h;
    } else if (m == 3) {                             // lane ≡3: level-5
        int j5 = (t >> 2) & (NPER5 - 1);
        if (j5 >= N0) s5 += h;
    }
}

__global__ void __launch_bounds__(TPB, 3)
gyro_main_kernel(const float* __restrict__ xs, const float* __restrict__ hx,
                 float* __restrict__ out, int cnt4, int cnt5) {
    int t0 = blockIdx.x * TPB + threadIdx.x;         // first half-group
    int t1 = t0 + HALF_STRIDE;                       // second half-group
    int lane = threadIdx.x & 31;

    // --- ALL loads front-issued: 12 float4 (hat) + 2 float4 (xs), MLP=14 ---
    const float4* hp0 = reinterpret_cast<const float4*>(hx) + (size_t)t0 * 6;
    const float4* hp1 = reinterpret_cast<const float4*>(hx) + (size_t)t1 * 6;
    float4 a0 = hp0[0], a1 = hp0[1], a2 = hp0[2], a3 = hp0[3], a4 = hp0[4], a5 = hp0[5];
    float4 b0 = hp1[0], b1 = hp1[1], b2 = hp1[2], b3 = hp1[3], b4 = hp1[4], b5 = hp1[5];
    float4 xv0 = *reinterpret_cast<const float4*>(xs + (size_t)(t0 >> 1) * 48);
    float4 xv1 = *reinterpret_cast<const float4*>(xs + (size_t)(t1 >> 1) * 48);

    float s4 = 0.0f, s5 = 0.0f;
    compute_half(t0, lane, a0, a1, a2, a3, a4, a5, xv0, s4, s5);
    compute_half(t1, lane, b0, b1, b2, b3, b4, b5, xv1, s4, s5);

    // --- reduction (R10 scheme) ---
#pragma unroll
    for (int off = 16; off > 0; off >>= 1) {
        s4 += __shfl_down_sync(0xFFFFFFFFu, s4, off);
        s5 += __shfl_down_sync(0xFFFFFFFFu, s5, off);
    }
    __shared__ float sh4[TPB / 32];
    __shared__ float sh5[TPB / 32];
    int warp = threadIdx.x >> 5;
    if (lane == 0) { sh4[warp] = s4; sh5[warp] = s5; }
    __syncthreads();

    if (threadIdx.x == 0) {
        float p4 = 0.0f, p5 = 0.0f;
#pragma unroll
        for (int w = 0; w < TPB / 32; w++) { p4 += sh4[w]; p5 += sh5[w]; }
        atomicAdd(&g_sum4, (double)p4);
        atomicAdd(&g_sum5, (double)p5);
        __threadfence();
        unsigned int ticket = atomicAdd(&g_count, 1u);
        if (ticket == gridDim.x - 1) {
            double s4t = atomicAdd(&g_sum4, 0.0);
            double s5t = atomicAdd(&g_sum5, 0.0);
            // loss = W*HUBER^2 * (mean4 + 0.5*mean5); W*HUBER^2 = 25
            double loss = 25.0 * (s4t / (double)cnt4 + 0.5 * s5t / (double)cnt5);
            out[0] = (float)loss;
            g_sum4 = 0.0;
            g_sum5 = 0.0;
            __threadfence();
            g_count = 0u;
        }
    }
}

extern "C" void kernel_launch(void* const* d_in, const int* in_sizes, int n_in,
                              void* d_out, int out_size) {
    const float* xs = (const float*)d_in[0];
    // d_in[1] = dp, unused by forward
    const float* hx = (const float*)d_in[2];

    int total = in_sizes[2];              // N*T*3 = 6291456
    int halves = total / 24;              // 262144 half-groups
    int groups = total / 48;              // 131072
    int nbatch = 64;
    int g4_per_batch = groups / nbatch;   // 2048
    int g5_per_batch = g4_per_batch / 2;  // 1024
    int cnt4 = nbatch * (g4_per_batch - N0) * 3;   // 392256
    int cnt5 = nbatch * (g5_per_batch - N0) * 3;   // 195648

    gyro_main_kernel<<<halves / (2 * TPB), TPB>>>(xs, hx, (float*)d_out, cnt4, cnt5);
}

// round 17
// speedup vs baseline: 1.0175x; 1.0175x over previous
#include <cuda_runtime.h>
#include <cstdint>

// GyroLoss forward — TMA-bulk double-buffered pipeline + R15 compute.
// TPB=128, 2 chunks per block (grid 1024). Each chunk's 12KB hat_xs slab is
// fetched by cp.async.bulk into smem (mbarrier complete_tx); chunk 1 loads
// while chunk 0 computes. xs via single LDG per chunk. R10 reduction.

#define DT_F 0.01f
#define HUBER_F 0.005f
#define NPER4 2048
#define NPER5 1024
#define N0 5
#define TPB 128
#define CHUNK_BYTES (TPB * 96)          // 12288 B of hat_xs per chunk

__device__ double g_sum4 = 0.0;
__device__ double g_sum5 = 0.0;
__device__ unsigned int g_count = 0u;

__device__ __forceinline__ uint32_t smem_u32(const void* p) {
    uint32_t a;
    asm("{ .reg .u64 t; cvta.to.shared.u64 t, %1; cvt.u32.u64 %0, t; }"
        : "=r"(a) : "l"(p));
    return a;
}

__device__ __forceinline__ void qmul(const float a[4], const float b[4], float c[4]) {
    c[0] = a[0]*b[0] - a[1]*b[1] - a[2]*b[2] - a[3]*b[3];
    c[1] = a[0]*b[1] + a[1]*b[0] + a[2]*b[3] - a[3]*b[2];
    c[2] = a[0]*b[2] - a[1]*b[3] + a[2]*b[0] + a[3]*b[1];
    c[3] = a[0]*b[3] + a[1]*b[2] - a[2]*b[1] + a[3]*b[0];
}

// c = conj(a) ⊗ b
__device__ __forceinline__ void qcmul(const float a[4], const float b[4], float c[4]) {
    c[0] = a[0]*b[0] + a[1]*b[1] + a[2]*b[2] + a[3]*b[3];
    c[1] = a[0]*b[1] - a[1]*b[0] - a[2]*b[3] + a[3]*b[2];
    c[2] = a[0]*b[2] + a[1]*b[3] - a[2]*b[0] - a[3]*b[1];
    c[3] = a[0]*b[3] - a[1]*b[2] + a[2]*b[1] - a[3]*b[0];
}

__device__ __forceinline__ void qexp_phi_small(float x, float y, float z, float q[4]) {
    float sq = x*x + y*y + z*z;
    float hq = 0.25f * sq;
    q[0] = 1.0f + hq * (-0.5f + hq * (1.0f / 24.0f));
    float sf = 0.5f * (1.0f + hq * (-(1.0f / 6.0f) + hq * (1.0f / 120.0f)));
    q[1] = sf * x; q[2] = sf * y; q[3] = sf * z;
}

__device__ __forceinline__ void qexp_full(float x, float y, float z, float q[4]) {
    float sq = x*x + y*y + z*z;
    float a = sq * __frsqrt_rn(fmaxf(sq, 1e-16f));
    float h = 0.5f * a;
    float sh = __sinf(h), ch = __cosf(h);
    float sf = __fdividef(sh, fmaxf(a, 1e-8f));
    q[0] = ch; q[1] = sf * x; q[2] = sf * y; q[3] = sf * z;
}

__device__ __forceinline__ float fast_atan01(float x) {
    float t = x * x;
    float p = -0.0117212f;
    p = fmaf(p, t,  0.05265332f);
    p = fmaf(p, t, -0.11643287f);
    p = fmaf(p, t,  0.19354346f);
    p = fmaf(p, t, -0.33262347f);
    p = fmaf(p, t,  0.99997726f);
    return x * p;
}

__device__ __forceinline__ float huber3_qlog(const float q[4]) {
    float w = q[0], x = q[1], y = q[2], z = q[3];
    float sg = (w < 0.0f) ? -1.0f : 1.0f;
    w *= sg; x *= sg; y *= sg; z *= sg;
    float nv2 = x*x + y*y + z*z;
    float nv = nv2 * __frsqrt_rn(fmaxf(nv2, 1e-24f));
    float lo = fminf(nv, w), hi = fmaxf(nv, w);
    float at = fast_atan01(__fdividef(lo, hi));
    float th = 2.0f * ((nv <= w) ? at : (1.57079632679f - at));
    float f = __fdividef(th, fmaxf(nv, 1e-20f)) * (1.0f / HUBER_F);
    float acc = 0.0f;
#pragma unroll
    for (int t = 0; t < 3; t++) {
        float zz = f * ((t == 0) ? x : (t == 1) ? y : z);
        float az = fabsf(zz);
        acc += (az < 1.0f) ? (0.5f * zz * zz) : (az - 0.5f);
    }
    return acc;
}

// BCH suffix-scan step (reverse time order): C += w x S; S += w
__device__ __forceinline__ void bch_step(float wx, float wy, float wz,
                                         float S[3], float C[3]) {
    C[0] = fmaf(wy, S[2], fmaf(-wz, S[1], C[0]));
    C[1] = fmaf(wz, S[0], fmaf(-wx, S[2], C[1]));
    C[2] = fmaf(wx, S[1], fmaf(-wy, S[0], C[2]));
    S[0] += wx; S[1] += wy; S[2] += wz;
}

// one half-group's full compute
__device__ __forceinline__ void compute_half(int t, int lane,
        float4 f0, float4 f1, float4 f2, float4 f3, float4 f4, float4 f5,
        float4 xv, float& s4, float& s5) {
    float S[3], C[3];
    S[0] = f5.y; S[1] = f5.z; S[2] = f5.w;           // incr 7
    C[0] = 0.0f; C[1] = 0.0f; C[2] = 0.0f;
    bch_step(f4.z, f4.w, f5.x, S, C);   // incr 6
    bch_step(f3.w, f4.x, f4.y, S, C);   // incr 5
    bch_step(f3.x, f3.y, f3.z, S, C);   // incr 4
    bch_step(f2.y, f2.z, f2.w, S, C);   // incr 3
    bch_step(f1.z, f1.w, f2.x, S, C);   // incr 2
    bch_step(f0.w, f1.x, f1.y, S, C);   // incr 1
    bch_step(f0.x, f0.y, f0.z, S, C);   // incr 0
    float q8[4];
    qexp_phi_small(fmaf(0.5f * DT_F * DT_F, C[0], DT_F * S[0]),
                   fmaf(0.5f * DT_F * DT_F, C[1], DT_F * S[1]),
                   fmaf(0.5f * DT_F * DT_F, C[2], DT_F * S[2]), q8);

    float q16[4];
    {
        float qp[4];
#pragma unroll
        for (int k = 0; k < 4; k++)
            qp[k] = __shfl_down_sync(0xFFFFFFFFu, q8[k], 1);
        qmul(q8, qp, q16);                           // valid on even lanes
    }

    float qR[4];
    qexp_full(xv.x, xv.y, xv.z, qR);

    int lb = lane & ~3;
    float q32[4], qR32[4];
    {
        float qa[4], qb[4], ra[4];
#pragma unroll
        for (int k = 0; k < 4; k++) {
            qa[k] = __shfl_sync(0xFFFFFFFFu, q16[k], lb);
            qb[k] = __shfl_sync(0xFFFFFFFFu, q16[k], lb | 2);
            ra[k] = __shfl_sync(0xFFFFFFFFu, qR[k],  lb);
        }
        qmul(qa, qb, q32);                           // used on lane ≡3
        qmul(ra, qR, qR32);
    }

    int m = t & 3;
    float relA[4], relB[4], rel[4];
    qcmul(q16, qR, relA);
    qcmul(q32, qR32, relB);
#pragma unroll
    for (int k = 0; k < 4; k++) rel[k] = (m == 3) ? relB[k] : relA[k];
    float h = huber3_qlog(rel);

    if ((m & 1) == 0) {
        int i4 = (t >> 1) & (NPER4 - 1);
        if (i4 >= N0) s4 += h;
    } else if (m == 3) {
        int j5 = (t >> 2) & (NPER5 - 1);
        if (j5 >= N0) s5 += h;
    }
}

__global__ void __launch_bounds__(TPB)
gyro_main_kernel(const float* __restrict__ xs, const float* __restrict__ hx,
                 float* __restrict__ out, int cnt4, int cnt5) {
    __shared__ __align__(16) float4 stage[2][TPB * 6];
    __shared__ __align__(8) unsigned long long mbar[2];
    __shared__ float sh4[TPB / 32];
    __shared__ float sh5[TPB / 32];

    int tid = threadIdx.x;
    int lane = tid & 31;
    uint32_t mb0 = smem_u32(&mbar[0]);
    uint32_t mb1 = smem_u32(&mbar[1]);

    if (tid == 0) {
        asm volatile("mbarrier.init.shared.b64 [%0], 1;" :: "r"(mb0) : "memory");
        asm volatile("mbarrier.init.shared.b64 [%0], 1;" :: "r"(mb1) : "memory");
    }
    __syncthreads();

    // issue both bulk copies up-front (chunk 1 streams while chunk 0 computes)
    if (tid == 0) {
        const char* src = reinterpret_cast<const char*>(hx)
                        + (size_t)blockIdx.x * (2 * CHUNK_BYTES);
        uint32_t d0 = smem_u32(&stage[0][0]);
        uint32_t d1 = smem_u32(&stage[1][0]);
        asm volatile("mbarrier.arrive.expect_tx.shared.b64 _, [%0], %1;"
                     :: "r"(mb0), "r"((uint32_t)CHUNK_BYTES) : "memory");
        asm volatile("cp.async.bulk.shared::cluster.global.mbarrier::complete_tx::bytes"
                     " [%0], [%1], %2, [%3];"
                     :: "r"(d0), "l"(src), "r"((uint32_t)CHUNK_BYTES), "r"(mb0)
                     : "memory");
        asm volatile("mbarrier.arrive.expect_tx.shared.b64 _, [%0], %1;"
                     :: "r"(mb1), "r"((uint32_t)CHUNK_BYTES) : "memory");
        asm volatile("cp.async.bulk.shared::cluster.global.mbarrier::complete_tx::bytes"
                     " [%0], [%1], %2, [%3];"
                     :: "r"(d1), "l"(src + CHUNK_BYTES), "r"((uint32_t)CHUNK_BYTES), "r"(mb1)
                     : "memory");
    }

    float s4 = 0.0f, s5 = 0.0f;

#pragma unroll
    for (int c = 0; c < 2; c++) {
        int t = blockIdx.x * (2 * TPB) + c * TPB + tid;   // half-group id
        // xs load (independent of smem pipeline)
        float4 xv = __ldg(reinterpret_cast<const float4*>(xs + (size_t)(t >> 1) * 48));

        // wait for this chunk's TMA completion (phase 0)
        uint32_t mb = (c == 0) ? mb0 : mb1;
        asm volatile(
            "{\n\t.reg .pred P;\n"
            "W%=:\n\t"
            "mbarrier.try_wait.parity.acquire.cta.shared::cta.b64 P, [%0], 0;\n\t"
            "@!P bra W%=;\n\t}"
            :: "r"(mb) : "memory");

        const float4* row = &stage[c][tid * 6];
        float4 f0 = row[0], f1 = row[1], f2 = row[2];
        float4 f3 = row[3], f4 = row[4], f5 = row[5];

        compute_half(t, lane, f0, f1, f2, f3, f4, f5, xv, s4, s5);
    }

    // --- reduction (R10 scheme) ---
#pragma unroll
    for (int off = 16; off > 0; off >>= 1) {
        s4 += __shfl_down_sync(0xFFFFFFFFu, s4, off);
        s5 += __shfl_down_sync(0xFFFFFFFFu, s5, off);
    }
    int warp = tid >> 5;
    if (lane == 0) { sh4[warp] = s4; sh5[warp] = s5; }
    __syncthreads();

    if (tid == 0) {
        float p4 = 0.0f, p5 = 0.0f;
#pragma unroll
        for (int w = 0; w < TPB / 32; w++) { p4 += sh4[w]; p5 += sh5[w]; }
        atomicAdd(&g_sum4, (double)p4);
        atomicAdd(&g_sum5, (double)p5);
        __threadfence();
        unsigned int ticket = atomicAdd(&g_count, 1u);
        if (ticket == gridDim.x - 1) {
            double s4t = atomicAdd(&g_sum4, 0.0);
            double s5t = atomicAdd(&g_sum5, 0.0);
            // loss = W*HUBER^2 * (mean4 + 0.5*mean5); W*HUBER^2 = 25
            double loss = 25.0 * (s4t / (double)cnt4 + 0.5 * s5t / (double)cnt5);
            out[0] = (float)loss;
            g_sum4 = 0.0;
            g_sum5 = 0.0;
            __threadfence();
            g_count = 0u;
        }
    }
}

extern "C" void kernel_launch(void* const* d_in, const int* in_sizes, int n_in,
                              void* d_out, int out_size) {
    const float* xs = (const float*)d_in[0];
    // d_in[1] = dp, unused by forward
    const float* hx = (const float*)d_in[2];

    int total = in_sizes[2];              // N*T*3 = 6291456
    int halves = total / 24;              // 262144 half-groups
    int groups = total / 48;              // 131072
    int nbatch = 64;
    int g4_per_batch = groups / nbatch;   // 2048
    int g5_per_batch = g4_per_batch / 2;  // 1024
    int cnt4 = nbatch * (g4_per_batch - N0) * 3;   // 392256
    int cnt5 = nbatch * (g5_per_batch - N0) * 3;   // 195648

    gyro_main_kernel<<<halves / (2 * TPB), TPB>>>(xs, hx, (float*)d_out, cnt4, cnt5);
}